// round 7
// baseline (speedup 1.0000x reference)
#include <cuda_runtime.h>
#include <cuda_bf16.h>
#include <math.h>
#include <stdint.h>

#define BB 32
#define CC 128
#define VV 64
#define TT 128
#define SP (VV*TT)   // 8192

// ---------------------------------------------------------------------------
// Scratch (device globals). Every kernel kept spill-free (mem-guard rule).
// ---------------------------------------------------------------------------
__device__ float g_buf1[(size_t)BB * 192 * SP]; // conv1 out [b][c][v][t]  192 MiB
__device__ float g_av [(size_t)BB * CC  * SP];  // [av_v 64 | av_t 64]     128 MiB
__device__ __nv_bfloat16 g_bufT[(size_t)BB * TT * 96 * VV]; // [b][t][c][v] 48 MiB
__device__ float g_mean [BB * CC];
__device__ float g_scale[BB * CC];
// packed bf16 weights: [chunk8][tap9][co][12 words] (words 0..7 = ci-pairs, 8..11 pad)
__device__ uint32_t g_w1[8 * 9 * 192 * 12];
__device__ uint32_t g_w2[8 * 9 * 128 * 12];

// ---------------------------------------------------------------------------
__device__ __forceinline__ uint32_t pack_bf16(float a, float b) {
    __nv_bfloat16 lo = __float2bfloat16(a), hi = __float2bfloat16(b);
    return ((uint32_t)__bfloat16_as_ushort(hi) << 16) | (uint32_t)__bfloat16_as_ushort(lo);
}

__device__ __forceinline__ void mma_bf16(
    float& d0, float& d1, float& d2, float& d3,
    uint32_t a0, uint32_t a1, uint32_t a2, uint32_t a3,
    uint32_t b0, uint32_t b1)
{
    asm volatile(
        "mma.sync.aligned.m16n8k16.row.col.f32.bf16.bf16.f32 "
        "{%0,%1,%2,%3}, {%4,%5,%6,%7}, {%8,%9}, {%0,%1,%2,%3};"
        : "+f"(d0), "+f"(d1), "+f"(d2), "+f"(d3)
        : "r"(a0), "r"(a1), "r"(a2), "r"(a3), "r"(b0), "r"(b1));
}

__device__ __forceinline__ void ldsm_x4(uint32_t& r0, uint32_t& r1,
                                        uint32_t& r2, uint32_t& r3, uint32_t addr)
{
    asm volatile("ldmatrix.sync.aligned.m8n8.x4.shared.b16 {%0,%1,%2,%3}, [%4];"
        : "=r"(r0), "=r"(r1), "=r"(r2), "=r"(r3) : "r"(addr));
}

__device__ __forceinline__ void ldsm_x2(uint32_t& r0, uint32_t& r1, uint32_t addr)
{
    asm volatile("ldmatrix.sync.aligned.m8n8.x2.shared.b16 {%0,%1}, [%2];"
        : "=r"(r0), "=r"(r1) : "r"(addr));
}

// ---------------------------------------------------------------------------
// Weight pre-conversion kernels
// ---------------------------------------------------------------------------
__global__ __launch_bounds__(256) void wcvt1_kernel(
    const float* __restrict__ v_qw, const float* __restrict__ v_kw,
    const float* __restrict__ v_vw,
    const float* __restrict__ t_qw, const float* __restrict__ t_kw,
    const float* __restrict__ t_vw)
{
    int idx = blockIdx.x * 256 + threadIdx.x;
    if (idx >= 8*9*192*12) return;
    int w    = idx % 12;
    int co   = (idx / 12) % 192;
    int tap  = (idx / (12*192)) % 9;
    int chunk= idx / (12*192*9);
    uint32_t val = 0;
    if (w < 8) {
        int ci = chunk*16 + w*2;
        const float* wb; int coL;
        if      (co < 16)  { wb = v_qw; coL = co;       }
        else if (co < 32)  { wb = v_kw; coL = co - 16;  }
        else if (co < 96)  { wb = v_vw; coL = co - 32;  }
        else if (co < 112) { wb = t_qw; coL = co - 96;  }
        else if (co < 128) { wb = t_kw; coL = co - 112; }
        else               { wb = t_vw; coL = co - 128; }
        float f0 = wb[(coL*CC + ci    )*9 + tap];
        float f1 = wb[(coL*CC + ci + 1)*9 + tap];
        val = pack_bf16(f0, f1);
    }
    g_w1[idx] = val;
}

__global__ __launch_bounds__(256) void wcvt2_kernel(
    const float* __restrict__ v_ow, const float* __restrict__ t_ow,
    const float* __restrict__ v_sigma, const float* __restrict__ t_sigma)
{
    int idx = blockIdx.x * 256 + threadIdx.x;
    if (idx >= 8*9*128*12) return;
    int w    = idx % 12;
    int co   = (idx / 12) % 128;
    int tap  = (idx / (12*128)) % 9;
    int chunk= idx / (12*128*9);
    uint32_t val = 0;
    if (w < 8) {
        int ci = chunk*16 + w*2;
        float f0, f1;
        if (ci < 64) {
            float s = v_sigma[0];
            f0 = v_ow[(co*64 + ci    )*9 + tap] * s;
            f1 = v_ow[(co*64 + ci + 1)*9 + tap] * s;
        } else {
            float s = t_sigma[0];
            f0 = t_ow[(co*64 + (ci-64))*9 + tap] * s;
            f1 = t_ow[(co*64 + (ci-63))*9 + tap] * s;
        }
        val = pack_bf16(f0, f1);
    }
    g_w2[idx] = val;
}

// ---------------------------------------------------------------------------
// bf16 implicit-GEMM conv core, ldmatrix edition.
// Block: 64 co x 128 pos (4v x 32t). 8 warps = 2(M co) x 4(N v-row).
// Warp tile 32co x 32t. m16n8k16, 8 ci-chunks of 16, 9 taps.
// xs: [6 v][34 t][12 words] ; ws: [9 tap][64 co][12 words] (48B row stride:
// the 8x16B rows of every ldmatrix tile land in disjoint bank groups).
// ---------------------------------------------------------------------------
__device__ __forceinline__ void conv_core_f(
    const float* __restrict__ src,
    const uint32_t* __restrict__ gw,
    int CO_TOT,
    int b, int co0, int v0, int t0,
    float acc[2][4][4])
{
    __shared__ uint32_t xs[6*34*12];
    __shared__ uint32_t ws[9*64*12];

    const int tid  = threadIdx.x;
    const int lane = tid & 31;
    const int warp = tid >> 5;
    const int wm = warp >> 2;
    const int wn = warp & 3;

    const uint32_t xs_s = (uint32_t)__cvta_generic_to_shared(xs);
    const uint32_t ws_s = (uint32_t)__cvta_generic_to_shared(ws);
    // per-thread ldmatrix row offsets (in words)
    const int aoff = (lane & 15) * 12 + ((lane >> 4) << 2);          // A: 32 rows, x4
    const int boff = (lane & 7) * 12 + (((lane >> 3) & 1) << 2);     // B: 16 rows, x2

    #pragma unroll
    for (int mt = 0; mt < 2; mt++)
        #pragma unroll
        for (int nt = 0; nt < 4; nt++)
            #pragma unroll
            for (int r = 0; r < 4; r++) acc[mt][nt][r] = 0.f;

    for (int chunk = 0; chunk < 8; chunk++) {
        // ---- fill xs: 6v x 8cp x 34t packed words ----
        for (int idx = tid; idx < 1632; idx += 256) {
            int v   = idx / 272;
            int rem = idx % 272;
            int cp  = rem / 34;
            int t   = rem % 34;
            int gv = v0 - 1 + v, gt = t0 - 1 + t;
            int ci = chunk*16 + cp*2;
            uint32_t val = 0;
            if (gv >= 0 && gv < VV && gt >= 0 && gt < TT) {
                const float* p = src + (((size_t)b*CC + ci)*VV + gv)*TT + gt;
                val = pack_bf16(p[0], p[SP]);
            }
            xs[(v*34 + t)*12 + cp] = val;
        }
        // ---- fill ws: raw uint4 copy ----
        {
            const uint4* src4 = (const uint4*)gw;
            uint4* dst4 = (uint4*)ws;
            for (int idx = tid; idx < 1728; idx += 256) {
                int tap = idx / 192;
                int w4  = idx % 192;
                dst4[tap*192 + w4] = src4[(size_t)((chunk*9 + tap)*CO_TOT + co0)*3 + w4];
            }
        }
        __syncthreads();

        // ---- compute: per tap, 2 ldsm.x4 (A) + 4 ldsm.x2 (B) + 8 MMA ----
        #pragma unroll
        for (int kh = 0; kh < 3; kh++) {
            #pragma unroll
            for (int kw = 0; kw < 3; kw++) {
                const int tap = kh*3 + kw;
                uint32_t a0[2], a1[2], a2[2], a3[2];
                #pragma unroll
                for (int mt = 0; mt < 2; mt++) {
                    uint32_t addrA = ws_s +
                        4u * (uint32_t)(tap*768 + (wm*32 + mt*16)*12 + aoff);
                    ldsm_x4(a0[mt], a1[mt], a2[mt], a3[mt], addrA);
                }
                const int rowbase = (wn + kh)*34 + kw;
                #pragma unroll
                for (int nt = 0; nt < 4; nt++) {
                    uint32_t b0, b1;
                    uint32_t addrB = xs_s +
                        4u * (uint32_t)((rowbase + nt*8)*12 + boff);
                    ldsm_x2(b0, b1, addrB);
                    #pragma unroll
                    for (int mt = 0; mt < 2; mt++)
                        mma_bf16(acc[mt][nt][0], acc[mt][nt][1],
                                 acc[mt][nt][2], acc[mt][nt][3],
                                 a0[mt], a1[mt], a2[mt], a3[mt], b0, b1);
                }
            }
        }
        __syncthreads();
    }
}

// ---------------------------------------------------------------------------
__global__ __launch_bounds__(256, 2) void conv1_mma_kernel(const float* __restrict__ x)
{
    const int tile = blockIdx.x;
    const int b = blockIdx.y;
    const int co0 = blockIdx.z * 64;
    const int v0 = (tile >> 2) * 4;
    const int t0 = (tile & 3) * 32;

    float acc[2][4][4];
    conv_core_f(x, g_w1, 192, b, co0, v0, t0, acc);

    const int lane = threadIdx.x & 31;
    const int warp = threadIdx.x >> 5;
    const int g  = lane >> 2;
    const int k4 = lane & 3;
    const int wm = warp >> 2;
    const int wn = warp & 3;
    const int v = v0 + wn;

    #pragma unroll
    for (int mt = 0; mt < 2; mt++) {
        #pragma unroll
        for (int nt = 0; nt < 4; nt++) {
            int coA = co0 + wm*32 + mt*16 + g;
            int coB = coA + 8;
            int t = t0 + nt*8 + k4*2;
            bool tA = (coA < 32) || (coA >= 96 && coA < 128);
            bool tB = (coB < 32) || (coB >= 96 && coB < 128);
            float r0 = acc[mt][nt][0], r1 = acc[mt][nt][1];
            float r2 = acc[mt][nt][2], r3 = acc[mt][nt][3];
            if (tA) { r0 = tanhf(r0); r1 = tanhf(r1); }
            if (tB) { r2 = tanhf(r2); r3 = tanhf(r3); }
            *(float2*)&g_buf1[(((size_t)b*192 + coA)*VV + v)*TT + t] = make_float2(r0, r1);
            *(float2*)&g_buf1[(((size_t)b*192 + coB)*VV + v)*TT + t] = make_float2(r2, r3);
        }
    }
}

__global__ __launch_bounds__(256, 2) void conv2_mma_kernel(
    const float* __restrict__ x, float* __restrict__ out)
{
    const int tile = blockIdx.x;
    const int b = blockIdx.y;
    const int co0 = blockIdx.z * 64;
    const int v0 = (tile >> 2) * 4;
    const int t0 = (tile & 3) * 32;

    float acc[2][4][4];
    conv_core_f(g_av, g_w2, 128, b, co0, v0, t0, acc);

    const int lane = threadIdx.x & 31;
    const int warp = threadIdx.x >> 5;
    const int g  = lane >> 2;
    const int k4 = lane & 3;
    const int wm = warp >> 2;
    const int wn = warp & 3;
    const int v = v0 + wn;

    #pragma unroll
    for (int mt = 0; mt < 2; mt++) {
        #pragma unroll
        for (int nt = 0; nt < 4; nt++) {
            int coA = co0 + wm*32 + mt*16 + g;
            int coB = coA + 8;
            int t = t0 + nt*8 + k4*2;
            size_t iA = (((size_t)b*CC + coA)*VV + v)*TT + t;
            size_t iB = (((size_t)b*CC + coB)*VV + v)*TT + t;
            float2 xA = *(const float2*)&x[iA];
            float2 xB = *(const float2*)&x[iB];
            float sA = g_scale[b*CC + coA];
            float sB = g_scale[b*CC + coB];
            *(float2*)&out[iA] = make_float2((xA.x + acc[mt][nt][0])*sA,
                                             (xA.y + acc[mt][nt][1])*sA);
            *(float2*)&out[iB] = make_float2((xB.x + acc[mt][nt][2])*sB,
                                             (xB.y + acc[mt][nt][3])*sB);
        }
    }
}

// ---------------------------------------------------------------------------
// t1: per b, transpose g_buf1 [6144 cv][128 t] (fp32) -> g_bufT [128 t][6144 cv] (bf16)
// ---------------------------------------------------------------------------
__global__ __launch_bounds__(256) void t1_kernel()
{
    __shared__ float tl[32][33];
    const int b = blockIdx.z;
    const float* ip = g_buf1 + (size_t)b * 192 * SP;
    __nv_bfloat16* op = g_bufT + (size_t)b * TT * 96 * 64;
    const int r0 = blockIdx.y * 32;   // cv
    const int c0 = blockIdx.x * 32;   // t
    const int tx = threadIdx.x & 31, ty = threadIdx.x >> 5;
    #pragma unroll
    for (int i = 0; i < 4; i++)
        tl[ty + i*8][tx] = ip[(size_t)(r0 + ty + i*8)*128 + c0 + tx];
    __syncthreads();
    #pragma unroll
    for (int i = 0; i < 4; i++)
        op[(size_t)(c0 + ty + i*8)*6144 + r0 + tx] = __float2bfloat16(tl[tx][ty + i*8]);
}

// ---------------------------------------------------------------------------
// t2: per b, transpose g_bufT [128 t][4096 cv (row stride 6144)] (bf16)
//     -> g_av v-path half [4096 cv][128 t] (fp32)
// ---------------------------------------------------------------------------
__global__ __launch_bounds__(256) void t2_kernel()
{
    __shared__ float tl[32][33];
    const int b = blockIdx.z;
    const __nv_bfloat16* ip = g_bufT + (size_t)b * TT * 96 * 64;
    float* op = g_av + (size_t)b * CC * SP;
    const int r0 = blockIdx.y * 32;   // t
    const int c0 = blockIdx.x * 32;   // cv
    const int tx = threadIdx.x & 31, ty = threadIdx.x >> 5;
    #pragma unroll
    for (int i = 0; i < 4; i++)
        tl[ty + i*8][tx] = __bfloat162float(ip[(size_t)(r0 + ty + i*8)*6144 + c0 + tx]);
    __syncthreads();
    #pragma unroll
    for (int i = 0; i < 4; i++)
        op[(size_t)(c0 + ty + i*8)*128 + r0 + tx] = tl[tx][ty + i*8];
}

// ---------------------------------------------------------------------------
// V-axis attention. Per (b,t). Coalesced bf16 loads; 4x4 register tiles;
// writes av in-place (first 64x64 of the slice).
// ---------------------------------------------------------------------------
__global__ __launch_bounds__(256) void attnV_kernel()
{
    __shared__ float Qs[16][65], Ks[16][65], Vs[64][65], L[64][65];
    const int b = blockIdx.x >> 7, t = blockIdx.x & 127;
    const int tid = threadIdx.x;
    const __nv_bfloat16* base = g_bufT + ((size_t)(b*TT + t)) * 96 * 64;

    for (int idx = tid; idx < 16*64; idx += 256) {
        int c = idx >> 6, v = idx & 63;
        Qs[c][v] = __bfloat162float(base[idx]);
        Ks[c][v] = __bfloat162float(base[16*64 + idx]);
    }
    for (int idx = tid; idx < 64*64; idx += 256) {
        int c = idx >> 6, v = idx & 63;
        Vs[c][v] = __bfloat162float(base[32*64 + idx]);
    }
    __syncthreads();

    {
        int w4 = (tid & 15) * 4, v4 = (tid >> 4) * 4;
        float l[4][4];
        #pragma unroll
        for (int i = 0; i < 4; i++)
            #pragma unroll
            for (int j = 0; j < 4; j++) l[i][j] = 0.f;
        #pragma unroll
        for (int c = 0; c < 16; c++) {
            float q[4], k[4];
            #pragma unroll
            for (int i = 0; i < 4; i++) q[i] = Qs[c][v4+i];
            #pragma unroll
            for (int j = 0; j < 4; j++) k[j] = Ks[c][w4+j];
            #pragma unroll
            for (int i = 0; i < 4; i++)
                #pragma unroll
                for (int j = 0; j < 4; j++) l[i][j] = fmaf(q[i], k[j], l[i][j]);
        }
        #pragma unroll
        for (int i = 0; i < 4; i++)
            #pragma unroll
            for (int j = 0; j < 4; j++) L[v4+i][w4+j] = l[i][j];
    }
    __syncthreads();

    {
        int row = tid >> 2, q = tid & 3;
        float m = -1e30f;
        #pragma unroll
        for (int j = 0; j < 16; j++) m = fmaxf(m, L[row][q*16 + j]);
        m = fmaxf(m, __shfl_xor_sync(0xffffffffu, m, 1));
        m = fmaxf(m, __shfl_xor_sync(0xffffffffu, m, 2));
        float s = 0.f;
        #pragma unroll
        for (int j = 0; j < 16; j++) {
            float e = __expf(L[row][q*16 + j] - m);
            L[row][q*16 + j] = e;
            s += e;
        }
        s += __shfl_xor_sync(0xffffffffu, s, 1);
        s += __shfl_xor_sync(0xffffffffu, s, 2);
        float inv = 1.f / s;
        #pragma unroll
        for (int j = 0; j < 16; j++) L[row][q*16 + j] *= inv;
    }
    __syncthreads();

    {
        int c4 = (tid & 15) * 4, v4 = (tid >> 4) * 4;
        float o[4][4];
        #pragma unroll
        for (int j = 0; j < 4; j++)
            #pragma unroll
            for (int i = 0; i < 4; i++) o[j][i] = 0.f;
        for (int w = 0; w < 64; w++) {
            float a[4], vv[4];
            #pragma unroll
            for (int i = 0; i < 4; i++) a[i] = L[v4+i][w];
            #pragma unroll
            for (int j = 0; j < 4; j++) vv[j] = Vs[c4+j][w];
            #pragma unroll
            for (int j = 0; j < 4; j++)
                #pragma unroll
                for (int i = 0; i < 4; i++) o[j][i] = fmaf(vv[j], a[i], o[j][i]);
        }
        __nv_bfloat16* outb = g_bufT + ((size_t)(b*TT + t)) * 96 * 64;
        #pragma unroll
        for (int j = 0; j < 4; j++) {
            __nv_bfloat162 p0, p1;
            p0.x = __float2bfloat16(o[j][0]); p0.y = __float2bfloat16(o[j][1]);
            p1.x = __float2bfloat16(o[j][2]); p1.y = __float2bfloat16(o[j][3]);
            *(__nv_bfloat162*)&outb[(c4+j)*64 + v4    ] = p0;
            *(__nv_bfloat162*)&outb[(c4+j)*64 + v4 + 2] = p1;
        }
    }
}

// ---------------------------------------------------------------------------
// T-axis attention. Per (b,v). fp32, coalesced loads, 4x4 register tiles.
// ---------------------------------------------------------------------------
__global__ __launch_bounds__(256) void attnT_kernel()
{
    extern __shared__ float sm[];
    float* Qs = sm;                       // [16][129]
    float* Ks = Qs + 16*129;              // [16][129]
    float* Vs = Ks + 16*129;              // [64][129]
    float* L  = Vs + 64*129;              // [128][129]
    const int b = blockIdx.x >> 6, v = blockIdx.x & 63;
    const int tid = threadIdx.x;
    const float* base = g_buf1 + (size_t)b * 192 * SP + (size_t)v * TT;

    for (int idx = tid; idx < 16*128; idx += 256) {
        int c = idx >> 7, t = idx & 127;
        Qs[c*129 + t] = base[(size_t)(96 + c)*SP + t];
        Ks[c*129 + t] = base[(size_t)(112 + c)*SP + t];
    }
    for (int idx = tid; idx < 64*128; idx += 256) {
        int c = idx >> 7, t = idx & 127;
        Vs[c*129 + t] = base[(size_t)(128 + c)*SP + t];
    }
    __syncthreads();

    #pragma unroll
    for (int rt = 0; rt < 2; rt++) {
        #pragma unroll
        for (int rs = 0; rs < 2; rs++) {
            int t4 = (tid >> 4)*4 + rt*64;
            int s4 = (tid & 15)*4 + rs*64;
            float l[4][4];
            #pragma unroll
            for (int i = 0; i < 4; i++)
                #pragma unroll
                for (int j = 0; j < 4; j++) l[i][j] = 0.f;
            #pragma unroll
            for (int c = 0; c < 16; c++) {
                float q[4], k[4];
                #pragma unroll
                for (int i = 0; i < 4; i++) q[i] = Qs[c*129 + t4+i];
                #pragma unroll
                for (int j = 0; j < 4; j++) k[j] = Ks[c*129 + s4+j];
                #pragma unroll
                for (int i = 0; i < 4; i++)
                    #pragma unroll
                    for (int j = 0; j < 4; j++) l[i][j] = fmaf(q[i], k[j], l[i][j]);
            }
            #pragma unroll
            for (int i = 0; i < 4; i++)
                #pragma unroll
                for (int j = 0; j < 4; j++) L[(t4+i)*129 + s4+j] = l[i][j];
        }
    }
    __syncthreads();

    {
        int row = tid >> 1, q = tid & 1;
        float* rp = L + row*129 + q*64;
        float m = -1e30f;
        #pragma unroll
        for (int j = 0; j < 64; j++) m = fmaxf(m, rp[j]);
        m = fmaxf(m, __shfl_xor_sync(0xffffffffu, m, 1));
        float s = 0.f;
        #pragma unroll
        for (int j = 0; j < 64; j++) { float e = __expf(rp[j] - m); rp[j] = e; s += e; }
        s += __shfl_xor_sync(0xffffffffu, s, 1);
        float inv = 1.f / s;
        #pragma unroll
        for (int j = 0; j < 64; j++) rp[j] *= inv;
    }
    __syncthreads();

    float* avb = g_av + (size_t)b * CC * SP + (size_t)64 * SP + (size_t)v * TT;
    #pragma unroll
    for (int rt = 0; rt < 2; rt++) {
        int c4 = (tid & 15)*4;
        int t4 = (tid >> 4)*4 + rt*64;
        float o[4][4];
        #pragma unroll
        for (int j = 0; j < 4; j++)
            #pragma unroll
            for (int i = 0; i < 4; i++) o[j][i] = 0.f;
        for (int s = 0; s < 128; s++) {
            float a[4], vv[4];
            #pragma unroll
            for (int i = 0; i < 4; i++) a[i] = L[(t4+i)*129 + s];
            #pragma unroll
            for (int j = 0; j < 4; j++) vv[j] = Vs[(c4+j)*129 + s];
            #pragma unroll
            for (int j = 0; j < 4; j++)
                #pragma unroll
                for (int i = 0; i < 4; i++) o[j][i] = fmaf(vv[j], a[i], o[j][i]);
        }
        #pragma unroll
        for (int j = 0; j < 4; j++) {
            *(float4*)&avb[(size_t)(c4+j)*SP + t4] =
                make_float4(o[j][0], o[j][1], o[j][2], o[j][3]);
        }
    }
}

// ---------------------------------------------------------------------------
// SE
// ---------------------------------------------------------------------------
__global__ __launch_bounds__(256) void se_mean_kernel(const float* __restrict__ x)
{
    __shared__ float red[256];
    const int bc = blockIdx.x;
    const float4* p = (const float4*)(x + (size_t)bc * SP);
    float s = 0.f;
    for (int i = threadIdx.x; i < SP/4; i += 256) {
        float4 f = p[i];
        s += f.x + f.y + f.z + f.w;
    }
    red[threadIdx.x] = s; __syncthreads();
    for (int off = 128; off > 0; off >>= 1) {
        if (threadIdx.x < off) red[threadIdx.x] += red[threadIdx.x + off];
        __syncthreads();
    }
    if (threadIdx.x == 0) g_mean[bc] = red[0] * (1.f / SP);
}

__global__ __launch_bounds__(128) void se_mlp_kernel(
    const float* __restrict__ w1, const float* __restrict__ w2)
{
    __shared__ float ym[128];
    __shared__ float h[8];
    const int b = blockIdx.x, tid = threadIdx.x;
    ym[tid] = g_mean[b*128 + tid];
    __syncthreads();
    if (tid < 8) {
        float s = 0.f;
        for (int c = 0; c < 128; c++) s += ym[c]*w1[tid*128 + c];
        h[tid] = s > 0.f ? s : 0.f;
    }
    __syncthreads();
    float s = 0.f;
    #pragma unroll
    for (int r = 0; r < 8; r++) s += h[r]*w2[tid*8 + r];
    g_scale[b*128 + tid] = 1.f/(1.f + expf(-s));
}

// ---------------------------------------------------------------------------
extern "C" void kernel_launch(void* const* d_in, const int* in_sizes, int n_in,
                              void* d_out, int out_size)
{
    const float* x     = (const float*)d_in[0];
    const float* v_qw  = (const float*)d_in[1];
    const float* v_kw  = (const float*)d_in[2];
    const float* v_vw  = (const float*)d_in[3];
    const float* v_ow  = (const float*)d_in[4];
    const float* v_sig = (const float*)d_in[5];
    const float* t_qw  = (const float*)d_in[6];
    const float* t_kw  = (const float*)d_in[7];
    const float* t_vw  = (const float*)d_in[8];
    const float* t_ow  = (const float*)d_in[9];
    const float* t_sig = (const float*)d_in[10];
    const float* se_w1 = (const float*)d_in[11];
    const float* se_w2 = (const float*)d_in[12];
    float* out = (float*)d_out;

    const int attnT_smem = (16*129 + 16*129 + 64*129 + 128*129) * 4; // 115584 B
    cudaFuncSetAttribute(attnT_kernel, cudaFuncAttributeMaxDynamicSharedMemorySize, attnT_smem);

    // weight pre-conversion
    wcvt1_kernel<<<(8*9*192*12 + 255)/256, 256>>>(v_qw, v_kw, v_vw, t_qw, t_kw, t_vw);
    wcvt2_kernel<<<(8*9*128*12 + 255)/256, 256>>>(v_ow, t_ow, v_sig, t_sig);

    // SE path (independent)
    se_mean_kernel<<<BB*CC, 256>>>(x);
    se_mlp_kernel<<<BB, 128>>>(se_w1, se_w2);

    conv1_mma_kernel<<<dim3(64, 32, 3), 256>>>(x);

    // v-path qkv -> [b][t][c][v] bf16
    t1_kernel<<<dim3(4, 192, BB), 256>>>();
    attnV_kernel<<<BB*TT, 256>>>();
    // attnV out -> g_av v-path half (fp32, [b][c][v][t])
    t2_kernel<<<dim3(128, 4, BB), 256>>>();

    attnT_kernel<<<BB*VV, 256, attnT_smem>>>();

    conv2_mma_kernel<<<dim3(64, 32, 2), 256>>>(x, out);
}

// round 9
// speedup vs baseline: 1.4161x; 1.4161x over previous
#include <cuda_runtime.h>
#include <cuda_bf16.h>
#include <math.h>
#include <stdint.h>

#define BB 32
#define CC 128
#define VV 64
#define TT 128
#define SP (VV*TT)   // 8192

// ---------------------------------------------------------------------------
// Scratch (device globals) — EXACTLY R6's proven footprint (~369 MiB).
// ---------------------------------------------------------------------------
__device__ float g_buf1[(size_t)BB * 192 * SP]; // conv1 out [b][c][v][t]  192 MiB
__device__ float g_av [(size_t)BB * CC  * SP];  // [av_v 64 | av_t 64]     128 MiB
__device__ __nv_bfloat16 g_bufT[(size_t)BB * TT * 96 * VV]; // [b][t][c][v] 48 MiB
__device__ float g_mean [BB * CC];
__device__ float g_scale[BB * CC];
// packed bf16 weights: [chunk8][tap9][co][12 words] (words 0..7 = ci-pairs, 8..11 pad)
__device__ __align__(16) uint32_t g_w1[8 * 9 * 192 * 12];
__device__ __align__(16) uint32_t g_w2[8 * 9 * 128 * 12];

// ---------------------------------------------------------------------------
__device__ __forceinline__ uint32_t pack_bf16(float a, float b) {
    __nv_bfloat16 lo = __float2bfloat16(a), hi = __float2bfloat16(b);
    return ((uint32_t)__bfloat16_as_ushort(hi) << 16) | (uint32_t)__bfloat16_as_ushort(lo);
}

__device__ __forceinline__ void mma_bf16(
    float& d0, float& d1, float& d2, float& d3,
    uint32_t a0, uint32_t a1, uint32_t a2, uint32_t a3,
    uint32_t b0, uint32_t b1)
{
    asm volatile(
        "mma.sync.aligned.m16n8k16.row.col.f32.bf16.bf16.f32 "
        "{%0,%1,%2,%3}, {%4,%5,%6,%7}, {%8,%9}, {%0,%1,%2,%3};"
        : "+f"(d0), "+f"(d1), "+f"(d2), "+f"(d3)
        : "r"(a0), "r"(a1), "r"(a2), "r"(a3), "r"(b0), "r"(b1));
}

__device__ __forceinline__ void cp_async16(uint32_t smem_addr, const void* gptr) {
    asm volatile("cp.async.cg.shared.global [%0], [%1], 16;"
                 :: "r"(smem_addr), "l"(gptr));
}
__device__ __forceinline__ void cp_commit() {
    asm volatile("cp.async.commit_group;");
}
__device__ __forceinline__ void cp_wait1() {
    asm volatile("cp.async.wait_group 1;");
}
__device__ __forceinline__ void cp_wait0() {
    asm volatile("cp.async.wait_group 0;");
}

// ---------------------------------------------------------------------------
// Weight pre-conversion kernels
// ---------------------------------------------------------------------------
__global__ __launch_bounds__(256) void wcvt1_kernel(
    const float* __restrict__ v_qw, const float* __restrict__ v_kw,
    const float* __restrict__ v_vw,
    const float* __restrict__ t_qw, const float* __restrict__ t_kw,
    const float* __restrict__ t_vw)
{
    int idx = blockIdx.x * 256 + threadIdx.x;
    if (idx >= 8*9*192*12) return;
    int w    = idx % 12;
    int co   = (idx / 12) % 192;
    int tap  = (idx / (12*192)) % 9;
    int chunk= idx / (12*192*9);
    uint32_t val = 0;
    if (w < 8) {
        int ci = chunk*16 + w*2;
        const float* wb; int coL;
        if      (co < 16)  { wb = v_qw; coL = co;       }
        else if (co < 32)  { wb = v_kw; coL = co - 16;  }
        else if (co < 96)  { wb = v_vw; coL = co - 32;  }
        else if (co < 112) { wb = t_qw; coL = co - 96;  }
        else if (co < 128) { wb = t_kw; coL = co - 112; }
        else               { wb = t_vw; coL = co - 128; }
        float f0 = wb[(coL*CC + ci    )*9 + tap];
        float f1 = wb[(coL*CC + ci + 1)*9 + tap];
        val = pack_bf16(f0, f1);
    }
    g_w1[idx] = val;
}

__global__ __launch_bounds__(256) void wcvt2_kernel(
    const float* __restrict__ v_ow, const float* __restrict__ t_ow,
    const float* __restrict__ v_sigma, const float* __restrict__ t_sigma)
{
    int idx = blockIdx.x * 256 + threadIdx.x;
    if (idx >= 8*9*128*12) return;
    int w    = idx % 12;
    int co   = (idx / 12) % 128;
    int tap  = (idx / (12*128)) % 9;
    int chunk= idx / (12*128*9);
    uint32_t val = 0;
    if (w < 8) {
        int ci = chunk*16 + w*2;
        float f0, f1;
        if (ci < 64) {
            float s = v_sigma[0];
            f0 = v_ow[(co*64 + ci    )*9 + tap] * s;
            f1 = v_ow[(co*64 + ci + 1)*9 + tap] * s;
        } else {
            float s = t_sigma[0];
            f0 = t_ow[(co*64 + (ci-64))*9 + tap] * s;
            f1 = t_ow[(co*64 + (ci-63))*9 + tap] * s;
        }
        val = pack_bf16(f0, f1);
    }
    g_w2[idx] = val;
}

// ---------------------------------------------------------------------------
// bf16 implicit-GEMM conv core (R6 geometry). Weights double-buffered via
// cp.async (no transform needed: g_w* is already in smem layout); x fill
// stays synchronous (needs fp32->bf16 pack).
// Block: 64 co x 128 pos (4v x 32t). 8 warps = 2(M) x 4(N v-row).
// Warp tile 32co x 32t, acc[2][4][4]. m16n8k16, 8 ci-chunks of 16, 9 taps.
// dyn smem: ws2[2][6912 w] + xs[2448 w] = 65088 B.
// ---------------------------------------------------------------------------
__device__ __forceinline__ void conv_core_f(
    const float* __restrict__ src,
    const uint32_t* __restrict__ gw,
    int CO_TOT,
    int b, int co0, int v0, int t0,
    float acc[2][4][4])
{
    extern __shared__ uint32_t dyn[];
    uint32_t* ws2 = dyn;            // 2 * 6912 words
    uint32_t* xs  = dyn + 13824;    // 2448 words: [6 v][34 t][12 cp-words]

    const int tid  = threadIdx.x;
    const int lane = tid & 31;
    const int warp = tid >> 5;
    const int g  = lane >> 2;
    const int k4 = lane & 3;
    const int wm = warp >> 2;
    const int wn = warp & 3;

    const uint32_t ws_s = (uint32_t)__cvta_generic_to_shared(ws2);

    #pragma unroll
    for (int mt = 0; mt < 2; mt++)
        #pragma unroll
        for (int nt = 0; nt < 4; nt++)
            #pragma unroll
            for (int r = 0; r < 4; r++) acc[mt][nt][r] = 0.f;

    // async weight prefetch for one chunk into buffer `buf`
    auto wfill = [&](int buf, int chunk) {
        for (int idx = tid; idx < 1728; idx += 256) {
            int tap = idx / 192;
            int w4  = idx % 192;
            const uint32_t* s = gw + (size_t)((chunk*9 + tap)*CO_TOT + co0)*12 + w4*4;
            cp_async16(ws_s + 4u*(uint32_t)(buf*6912 + tap*768 + w4*4), s);
        }
        cp_commit();
    };

    wfill(0, 0);                       // group: w0
    for (int chunk = 0; chunk < 8; chunk++) {
        const int buf = chunk & 1;
        // ---- fill xs synchronously (pack fp32 -> bf16 pair) ----
        for (int idx = tid; idx < 1632; idx += 256) {
            int v   = idx / 272;
            int rem = idx % 272;
            int cp  = rem / 34;
            int t   = rem % 34;
            int gv = v0 - 1 + v, gt = t0 - 1 + t;
            int ci = chunk*16 + cp*2;
            uint32_t val = 0;
            if (gv >= 0 && gv < VV && gt >= 0 && gt < TT) {
                const float* p = src + (((size_t)b*CC + ci)*VV + gv)*TT + gt;
                val = pack_bf16(p[0], p[SP]);
            }
            xs[(v*34 + t)*12 + cp] = val;
        }
        // ---- prefetch next chunk's weights, then wait for current ----
        if (chunk < 7) { wfill(buf ^ 1, chunk + 1); cp_wait1(); }
        else           { cp_wait0(); }
        __syncthreads();

        const uint32_t* wsb = ws2 + buf*6912;
        #pragma unroll
        for (int kh = 0; kh < 3; kh++) {
            #pragma unroll
            for (int kw = 0; kw < 3; kw++) {
                const int tap = kh*3 + kw;
                const uint32_t* wt = wsb + tap*768;
                uint32_t a0[2], a1[2], a2[2], a3[2];
                #pragma unroll
                for (int mt = 0; mt < 2; mt++) {
                    const uint32_t* p = wt + (wm*32 + mt*16 + g) * 12;
                    a0[mt] = p[k4];
                    a2[mt] = p[k4+4];
                    a1[mt] = p[96 + k4];
                    a3[mt] = p[96 + k4+4];
                }
                const uint32_t* xrow = xs + ((wn + kh)*34 + g + kw) * 12;
                #pragma unroll
                for (int nt = 0; nt < 4; nt++) {
                    const uint32_t* xr = xrow + nt*96;
                    uint32_t b0 = xr[k4];
                    uint32_t b1 = xr[k4+4];
                    #pragma unroll
                    for (int mt = 0; mt < 2; mt++)
                        mma_bf16(acc[mt][nt][0], acc[mt][nt][1],
                                 acc[mt][nt][2], acc[mt][nt][3],
                                 a0[mt], a1[mt], a2[mt], a3[mt], b0, b1);
                }
            }
        }
        __syncthreads();
    }
}

// ---------------------------------------------------------------------------
__global__ __launch_bounds__(256) void conv1_mma_kernel(const float* __restrict__ x)
{
    const int tile = blockIdx.x;
    const int b = blockIdx.y;
    const int co0 = blockIdx.z * 64;
    const int v0 = (tile >> 2) * 4;
    const int t0 = (tile & 3) * 32;

    float acc[2][4][4];
    conv_core_f(x, g_w1, 192, b, co0, v0, t0, acc);

    const int lane = threadIdx.x & 31;
    const int warp = threadIdx.x >> 5;
    const int g  = lane >> 2;
    const int k4 = lane & 3;
    const int wm = warp >> 2;
    const int wn = warp & 3;
    const int v = v0 + wn;

    #pragma unroll
    for (int mt = 0; mt < 2; mt++) {
        #pragma unroll
        for (int nt = 0; nt < 4; nt++) {
            int coA = co0 + wm*32 + mt*16 + g;
            int coB = coA + 8;
            int t = t0 + nt*8 + k4*2;
            bool tA = (coA < 32) || (coA >= 96 && coA < 128);
            bool tB = (coB < 32) || (coB >= 96 && coB < 128);
            float r0 = acc[mt][nt][0], r1 = acc[mt][nt][1];
            float r2 = acc[mt][nt][2], r3 = acc[mt][nt][3];
            if (tA) { r0 = tanhf(r0); r1 = tanhf(r1); }
            if (tB) { r2 = tanhf(r2); r3 = tanhf(r3); }
            *(float2*)&g_buf1[(((size_t)b*192 + coA)*VV + v)*TT + t] = make_float2(r0, r1);
            *(float2*)&g_buf1[(((size_t)b*192 + coB)*VV + v)*TT + t] = make_float2(r2, r3);
        }
    }
}

__global__ __launch_bounds__(256) void conv2_mma_kernel(
    const float* __restrict__ x, float* __restrict__ out)
{
    const int tile = blockIdx.x;
    const int b = blockIdx.y;
    const int co0 = blockIdx.z * 64;
    const int v0 = (tile >> 2) * 4;
    const int t0 = (tile & 3) * 32;

    float acc[2][4][4];
    conv_core_f(g_av, g_w2, 128, b, co0, v0, t0, acc);

    const int lane = threadIdx.x & 31;
    const int warp = threadIdx.x >> 5;
    const int g  = lane >> 2;
    const int k4 = lane & 3;
    const int wm = warp >> 2;
    const int wn = warp & 3;
    const int v = v0 + wn;

    #pragma unroll
    for (int mt = 0; mt < 2; mt++) {
        #pragma unroll
        for (int nt = 0; nt < 4; nt++) {
            int coA = co0 + wm*32 + mt*16 + g;
            int coB = coA + 8;
            int t = t0 + nt*8 + k4*2;
            size_t iA = (((size_t)b*CC + coA)*VV + v)*TT + t;
            size_t iB = (((size_t)b*CC + coB)*VV + v)*TT + t;
            float2 xA = *(const float2*)&x[iA];
            float2 xB = *(const float2*)&x[iB];
            float sA = g_scale[b*CC + coA];
            float sB = g_scale[b*CC + coB];
            *(float2*)&out[iA] = make_float2((xA.x + acc[mt][nt][0])*sA,
                                             (xA.y + acc[mt][nt][1])*sA);
            *(float2*)&out[iB] = make_float2((xB.x + acc[mt][nt][2])*sB,
                                             (xB.y + acc[mt][nt][3])*sB);
        }
    }
}

// ---------------------------------------------------------------------------
// t1: per b, transpose g_buf1 [6144 cv][128 t] (fp32) -> g_bufT [128 t][6144 cv] (bf16)
// ---------------------------------------------------------------------------
__global__ __launch_bounds__(256) void t1_kernel()
{
    __shared__ float tl[32][33];
    const int b = blockIdx.z;
    const float* ip = g_buf1 + (size_t)b * 192 * SP;
    __nv_bfloat16* op = g_bufT + (size_t)b * TT * 96 * 64;
    const int r0 = blockIdx.y * 32;   // cv
    const int c0 = blockIdx.x * 32;   // t
    const int tx = threadIdx.x & 31, ty = threadIdx.x >> 5;
    #pragma unroll
    for (int i = 0; i < 4; i++)
        tl[ty + i*8][tx] = ip[(size_t)(r0 + ty + i*8)*128 + c0 + tx];
    __syncthreads();
    #pragma unroll
    for (int i = 0; i < 4; i++)
        op[(size_t)(c0 + ty + i*8)*6144 + r0 + tx] = __float2bfloat16(tl[tx][ty + i*8]);
}

// ---------------------------------------------------------------------------
// t2: per b, transpose g_bufT [128 t][4096 cv (row stride 6144)] (bf16)
//     -> g_av v-path half [4096 cv][128 t] (fp32)
// ---------------------------------------------------------------------------
__global__ __launch_bounds__(256) void t2_kernel()
{
    __shared__ float tl[32][33];
    const int b = blockIdx.z;
    const __nv_bfloat16* ip = g_bufT + (size_t)b * TT * 96 * 64;
    float* op = g_av + (size_t)b * CC * SP;
    const int r0 = blockIdx.y * 32;   // t
    const int c0 = blockIdx.x * 32;   // cv
    const int tx = threadIdx.x & 31, ty = threadIdx.x >> 5;
    #pragma unroll
    for (int i = 0; i < 4; i++)
        tl[ty + i*8][tx] = __bfloat162float(ip[(size_t)(r0 + ty + i*8)*6144 + c0 + tx]);
    __syncthreads();
    #pragma unroll
    for (int i = 0; i < 4; i++)
        op[(size_t)(c0 + ty + i*8)*128 + r0 + tx] = tl[tx][ty + i*8];
}

// ---------------------------------------------------------------------------
// V-axis attention. Per (b,t). Coalesced bf16 loads; 4x4 register tiles;
// writes av in-place (first 64x64 of the slice).
// ---------------------------------------------------------------------------
__global__ __launch_bounds__(256) void attnV_kernel()
{
    __shared__ float Qs[16][65], Ks[16][65], Vs[64][65], L[64][65];
    const int b = blockIdx.x >> 7, t = blockIdx.x & 127;
    const int tid = threadIdx.x;
    const __nv_bfloat16* base = g_bufT + ((size_t)(b*TT + t)) * 96 * 64;

    for (int idx = tid; idx < 16*64; idx += 256) {
        int c = idx >> 6, v = idx & 63;
        Qs[c][v] = __bfloat162float(base[idx]);
        Ks[c][v] = __bfloat162float(base[16*64 + idx]);
    }
    for (int idx = tid; idx < 64*64; idx += 256) {
        int c = idx >> 6, v = idx & 63;
        Vs[c][v] = __bfloat162float(base[32*64 + idx]);
    }
    __syncthreads();

    {
        int w4 = (tid & 15) * 4, v4 = (tid >> 4) * 4;
        float l[4][4];
        #pragma unroll
        for (int i = 0; i < 4; i++)
            #pragma unroll
            for (int j = 0; j < 4; j++) l[i][j] = 0.f;
        #pragma unroll
        for (int c = 0; c < 16; c++) {
            float q[4], k[4];
            #pragma unroll
            for (int i = 0; i < 4; i++) q[i] = Qs[c][v4+i];
            #pragma unroll
            for (int j = 0; j < 4; j++) k[j] = Ks[c][w4+j];
            #pragma unroll
            for (int i = 0; i < 4; i++)
                #pragma unroll
                for (int j = 0; j < 4; j++) l[i][j] = fmaf(q[i], k[j], l[i][j]);
        }
        #pragma unroll
        for (int i = 0; i < 4; i++)
            #pragma unroll
            for (int j = 0; j < 4; j++) L[v4+i][w4+j] = l[i][j];
    }
    __syncthreads();

    {
        int row = tid >> 2, q = tid & 3;
        float m = -1e30f;
        #pragma unroll
        for (int j = 0; j < 16; j++) m = fmaxf(m, L[row][q*16 + j]);
        m = fmaxf(m, __shfl_xor_sync(0xffffffffu, m, 1));
        m = fmaxf(m, __shfl_xor_sync(0xffffffffu, m, 2));
        float s = 0.f;
        #pragma unroll
        for (int j = 0; j < 16; j++) {
            float e = __expf(L[row][q*16 + j] - m);
            L[row][q*16 + j] = e;
            s += e;
        }
        s += __shfl_xor_sync(0xffffffffu, s, 1);
        s += __shfl_xor_sync(0xffffffffu, s, 2);
        float inv = 1.f / s;
        #pragma unroll
        for (int j = 0; j < 16; j++) L[row][q*16 + j] *= inv;
    }
    __syncthreads();

    {
        int c4 = (tid & 15) * 4, v4 = (tid >> 4) * 4;
        float o[4][4];
        #pragma unroll
        for (int j = 0; j < 4; j++)
            #pragma unroll
            for (int i = 0; i < 4; i++) o[j][i] = 0.f;
        for (int w = 0; w < 64; w++) {
            float a[4], vv[4];
            #pragma unroll
            for (int i = 0; i < 4; i++) a[i] = L[v4+i][w];
            #pragma unroll
            for (int j = 0; j < 4; j++) vv[j] = Vs[c4+j][w];
            #pragma unroll
            for (int j = 0; j < 4; j++)
                #pragma unroll
                for (int i = 0; i < 4; i++) o[j][i] = fmaf(vv[j], a[i], o[j][i]);
        }
        __nv_bfloat16* outb = g_bufT + ((size_t)(b*TT + t)) * 96 * 64;
        #pragma unroll
        for (int j = 0; j < 4; j++) {
            __nv_bfloat162 p0, p1;
            p0.x = __float2bfloat16(o[j][0]); p0.y = __float2bfloat16(o[j][1]);
            p1.x = __float2bfloat16(o[j][2]); p1.y = __float2bfloat16(o[j][3]);
            *(__nv_bfloat162*)&outb[(c4+j)*64 + v4    ] = p0;
            *(__nv_bfloat162*)&outb[(c4+j)*64 + v4 + 2] = p1;
        }
    }
}

// ---------------------------------------------------------------------------
// T-axis attention. Per (b,v). fp32, coalesced loads, 4x4 register tiles.
// ---------------------------------------------------------------------------
__global__ __launch_bounds__(256) void attnT_kernel()
{
    extern __shared__ float sm[];
    float* Qs = sm;                       // [16][129]
    float* Ks = Qs + 16*129;              // [16][129]
    float* Vs = Ks + 16*129;              // [64][129]
    float* L  = Vs + 64*129;              // [128][129]
    const int b = blockIdx.x >> 6, v = blockIdx.x & 63;
    const int tid = threadIdx.x;
    const float* base = g_buf1 + (size_t)b * 192 * SP + (size_t)v * TT;

    for (int idx = tid; idx < 16*128; idx += 256) {
        int c = idx >> 7, t = idx & 127;
        Qs[c*129 + t] = base[(size_t)(96 + c)*SP + t];
        Ks[c*129 + t] = base[(size_t)(112 + c)*SP + t];
    }
    for (int idx = tid; idx < 64*128; idx += 256) {
        int c = idx >> 7, t = idx & 127;
        Vs[c*129 + t] = base[(size_t)(128 + c)*SP + t];
    }
    __syncthreads();

    #pragma unroll
    for (int rt = 0; rt < 2; rt++) {
        #pragma unroll
        for (int rs = 0; rs < 2; rs++) {
            int t4 = (tid >> 4)*4 + rt*64;
            int s4 = (tid & 15)*4 + rs*64;
            float l[4][4];
            #pragma unroll
            for (int i = 0; i < 4; i++)
                #pragma unroll
                for (int j = 0; j < 4; j++) l[i][j] = 0.f;
            #pragma unroll
            for (int c = 0; c < 16; c++) {
                float q[4], k[4];
                #pragma unroll
                for (int i = 0; i < 4; i++) q[i] = Qs[c*129 + t4+i];
                #pragma unroll
                for (int j = 0; j < 4; j++) k[j] = Ks[c*129 + s4+j];
                #pragma unroll
                for (int i = 0; i < 4; i++)
                    #pragma unroll
                    for (int j = 0; j < 4; j++) l[i][j] = fmaf(q[i], k[j], l[i][j]);
            }
            #pragma unroll
            for (int i = 0; i < 4; i++)
                #pragma unroll
                for (int j = 0; j < 4; j++) L[(t4+i)*129 + s4+j] = l[i][j];
        }
    }
    __syncthreads();

    {
        int row = tid >> 1, q = tid & 1;
        float* rp = L + row*129 + q*64;
        float m = -1e30f;
        #pragma unroll
        for (int j = 0; j < 64; j++) m = fmaxf(m, rp[j]);
        m = fmaxf(m, __shfl_xor_sync(0xffffffffu, m, 1));
        float s = 0.f;
        #pragma unroll
        for (int j = 0; j < 64; j++) { float e = __expf(rp[j] - m); rp[j] = e; s += e; }
        s += __shfl_xor_sync(0xffffffffu, s, 1);
        float inv = 1.f / s;
        #pragma unroll
        for (int j = 0; j < 64; j++) rp[j] *= inv;
    }
    __syncthreads();

    float* avb = g_av + (size_t)b * CC * SP + (size_t)64 * SP + (size_t)v * TT;
    #pragma unroll
    for (int rt = 0; rt < 2; rt++) {
        int c4 = (tid & 15)*4;
        int t4 = (tid >> 4)*4 + rt*64;
        float o[4][4];
        #pragma unroll
        for (int j = 0; j < 4; j++)
            #pragma unroll
            for (int i = 0; i < 4; i++) o[j][i] = 0.f;
        for (int s = 0; s < 128; s++) {
            float a[4], vv[4];
            #pragma unroll
            for (int i = 0; i < 4; i++) a[i] = L[(t4+i)*129 + s];
            #pragma unroll
            for (int j = 0; j < 4; j++) vv[j] = Vs[(c4+j)*129 + s];
            #pragma unroll
            for (int j = 0; j < 4; j++)
                #pragma unroll
                for (int i = 0; i < 4; i++) o[j][i] = fmaf(vv[j], a[i], o[j][i]);
        }
        #pragma unroll
        for (int j = 0; j < 4; j++) {
            *(float4*)&avb[(size_t)(c4+j)*SP + t4] =
                make_float4(o[j][0], o[j][1], o[j][2], o[j][3]);
        }
    }
}

// ---------------------------------------------------------------------------
// SE
// ---------------------------------------------------------------------------
__global__ __launch_bounds__(256) void se_mean_kernel(const float* __restrict__ x)
{
    __shared__ float red[256];
    const int bc = blockIdx.x;
    const float4* p = (const float4*)(x + (size_t)bc * SP);
    float s = 0.f;
    for (int i = threadIdx.x; i < SP/4; i += 256) {
        float4 f = p[i];
        s += f.x + f.y + f.z + f.w;
    }
    red[threadIdx.x] = s; __syncthreads();
    for (int off = 128; off > 0; off >>= 1) {
        if (threadIdx.x < off) red[threadIdx.x] += red[threadIdx.x + off];
        __syncthreads();
    }
    if (threadIdx.x == 0) g_mean[bc] = red[0] * (1.f / SP);
}

__global__ __launch_bounds__(128) void se_mlp_kernel(
    const float* __restrict__ w1, const float* __restrict__ w2)
{
    __shared__ float ym[128];
    __shared__ float h[8];
    const int b = blockIdx.x, tid = threadIdx.x;
    ym[tid] = g_mean[b*128 + tid];
    __syncthreads();
    if (tid < 8) {
        float s = 0.f;
        for (int c = 0; c < 128; c++) s += ym[c]*w1[tid*128 + c];
        h[tid] = s > 0.f ? s : 0.f;
    }
    __syncthreads();
    float s = 0.f;
    #pragma unroll
    for (int r = 0; r < 8; r++) s += h[r]*w2[tid*8 + r];
    g_scale[b*128 + tid] = 1.f/(1.f + expf(-s));
}

// ---------------------------------------------------------------------------
extern "C" void kernel_launch(void* const* d_in, const int* in_sizes, int n_in,
                              void* d_out, int out_size)
{
    const float* x     = (const float*)d_in[0];
    const float* v_qw  = (const float*)d_in[1];
    const float* v_kw  = (const float*)d_in[2];
    const float* v_vw  = (const float*)d_in[3];
    const float* v_ow  = (const float*)d_in[4];
    const float* v_sig = (const float*)d_in[5];
    const float* t_qw  = (const float*)d_in[6];
    const float* t_kw  = (const float*)d_in[7];
    const float* t_vw  = (const float*)d_in[8];
    const float* t_ow  = (const float*)d_in[9];
    const float* t_sig = (const float*)d_in[10];
    const float* se_w1 = (const float*)d_in[11];
    const float* se_w2 = (const float*)d_in[12];
    float* out = (float*)d_out;

    const int attnT_smem = (16*129 + 16*129 + 64*129 + 128*129) * 4; // 115584 B
    cudaFuncSetAttribute(attnT_kernel, cudaFuncAttributeMaxDynamicSharedMemorySize, attnT_smem);
    const int conv_smem = (2*6912 + 2448) * 4; // 65088 B
    cudaFuncSetAttribute(conv1_mma_kernel, cudaFuncAttributeMaxDynamicSharedMemorySize, conv_smem);
    cudaFuncSetAttribute(conv2_mma_kernel, cudaFuncAttributeMaxDynamicSharedMemorySize, conv_smem);

    // weight pre-conversion
    wcvt1_kernel<<<(8*9*192*12 + 255)/256, 256>>>(v_qw, v_kw, v_vw, t_qw, t_kw, t_vw);
    wcvt2_kernel<<<(8*9*128*12 + 255)/256, 256>>>(v_ow, t_ow, v_sig, t_sig);

    // SE path (independent)
    se_mean_kernel<<<BB*CC, 256>>>(x);
    se_mlp_kernel<<<BB, 128>>>(se_w1, se_w2);

    conv1_mma_kernel<<<dim3(64, 32, 3), 256, conv_smem>>>(x);

    // v-path qkv -> [b][t][c][v] bf16
    t1_kernel<<<dim3(4, 192, BB), 256>>>();
    attnV_kernel<<<BB*TT, 256>>>();
    // attnV out -> g_av v-path half (fp32, [b][c][v][t])
    t2_kernel<<<dim3(128, 4, BB), 256>>>();

    attnT_kernel<<<BB*VV, 256, attnT_smem>>>();

    conv2_mma_kernel<<<dim3(64, 32, 2), 256, conv_smem>>>(x, out);
}